// round 11
// baseline (speedup 1.0000x reference)
#include <cuda_runtime.h>

// Problem constants (shapes fixed by the reference).
#define B_SZ   32768
#define D_SZ   128
#define H_SZ   64
#define NSTEP  32
#define ROWS   32       // batch rows per CTA
#define NTHR   256
#define NCTA   (B_SZ / ROWS)   // 1024

// Packed K-major weights (prologue-built, read-only after).
// Gate GEMM layout: W[k][256] where position p encodes
//   p < 128 : gates i,f  -> p = ln*4 + g*2 + j2      (g in {0,1})
//   p >=128 : gates g,o  -> p = 128 + ln*4 + (g-2)*2 + j2
// mapping to logical gate column c = 64*g + 2*ln + j2.
// Lane ln loads float4 at [k*256 + ln*4]      = (i0,i1,f0,f1) = 2 f32x2 pairs
//          and float4 at [k*256 + 128 + ln*4] = (g0,g1,o0,o1) = 2 f32x2 pairs
// both fully coalesced (512 B per warp per LDG.128).
__device__ __align__(16) float g_W0p[192 * 256];   // rows 0..127 Wih0^T, 128..191 Whh0^T
__device__ __align__(16) float g_W1p[128 * 256];   // rows 0..63  Wih1^T, 64..127  Whh1^T
__device__ __align__(16) float g_Wfct[64 * 128];   // plain Wfc^T (K-major)

__global__ void pack_weights(const float* __restrict__ Wih0,
                             const float* __restrict__ Whh0,
                             const float* __restrict__ Wih1,
                             const float* __restrict__ Whh1,
                             const float* __restrict__ Wfc)
{
    int i = blockIdx.x * blockDim.x + threadIdx.x;
    const int S0 = 192 * 256;
    const int S1 = S0 + 128 * 256;
    const int S2 = S1 + 64 * 128;
    if (i < S0) {
        int k = i >> 8, p = i & 255;
        int half = p >> 7, q = p & 127;
        int ln = q >> 2, g = half * 2 + ((q >> 1) & 1), j2 = q & 1;
        int c = 64 * g + 2 * ln + j2;
        g_W0p[i] = (k < 128) ? Wih0[c * 128 + k] : Whh0[c * 64 + (k - 128)];
    } else if (i < S1) {
        int ii = i - S0;
        int k = ii >> 8, p = ii & 255;
        int half = p >> 7, q = p & 127;
        int ln = q >> 2, g = half * 2 + ((q >> 1) & 1), j2 = q & 1;
        int c = 64 * g + 2 * ln + j2;
        g_W1p[ii] = (k < 64) ? Wih1[c * 64 + k] : Whh1[c * 64 + (k - 64)];
    } else if (i < S2) {
        int ii = i - S1;
        int k = ii >> 7, n = ii & 127;
        g_Wfct[ii] = Wfc[n * 64 + k];
    }
}

// ---- f32x2 helpers -------------------------------------------------------
typedef unsigned long long u64t;

__device__ __forceinline__ u64t dup1(float x) {
    u64t r;
    asm("mov.b64 %0, {%1, %1};" : "=l"(r) : "f"(x));
    return r;
}
__device__ __forceinline__ void unpack2(u64t v, float& x, float& y) {
    asm("mov.b64 {%0, %1}, %2;" : "=f"(x), "=f"(y) : "l"(v));
}
__device__ __forceinline__ void ffma2(u64t& d, u64t a, u64t b) {
    asm("fma.rn.f32x2 %0, %1, %2, %0;" : "+l"(d) : "l"(a), "l"(b));
}

__device__ __forceinline__ float sigf(float x) {
    return __fdividef(1.0f, 1.0f + __expf(-x));
}
__device__ __forceinline__ float tanhfast(float x) {
    return __fdividef(2.0f, 1.0f + __expf(-2.0f * x)) - 1.0f;
}

// C[32 x 256] += A[32 x K] * Wp[K x 256] in the packed-gate layout.
// Warp w owns rows w*4..w*4+3; lane ln owns cols 2ln/2ln+1 of each gate.
// acc[m][g] is an f32x2 pair for gate g, row w*4+m.
// Weight loads kept inside the e-loop to minimize live registers
// (3-CTA occupancy needs <=85 regs/thread).
template <int K, int LDA>
__device__ __forceinline__ void gemm256f(u64t acc[4][4],
                                         const float* __restrict__ As,
                                         const float* __restrict__ Wp,
                                         int w, int ln)
{
#pragma unroll 2
    for (int kk = 0; kk < K; kk += 4) {
        float4 a[4];
#pragma unroll
        for (int m = 0; m < 4; ++m)
            a[m] = *(const float4*)(As + (w * 4 + m) * LDA + kk);
#pragma unroll
        for (int e = 0; e < 4; ++e) {
            ulonglong2 bif = *(const ulonglong2*)(Wp + (kk + e) * 256 + ln * 4);
            ulonglong2 bgo = *(const ulonglong2*)(Wp + (kk + e) * 256 + 128 + ln * 4);
            float av[4] = {e == 0 ? a[0].x : e == 1 ? a[0].y : e == 2 ? a[0].z : a[0].w,
                           e == 0 ? a[1].x : e == 1 ? a[1].y : e == 2 ? a[1].z : a[1].w,
                           e == 0 ? a[2].x : e == 1 ? a[2].y : e == 2 ? a[2].z : a[2].w,
                           e == 0 ? a[3].x : e == 1 ? a[3].y : e == 2 ? a[3].z : a[3].w};
#pragma unroll
            for (int m = 0; m < 4; ++m) {
                u64t ad = dup1(av[m]);
                ffma2(acc[m][0], ad, bif.x);
                ffma2(acc[m][1], ad, bif.y);
                ffma2(acc[m][2], ad, bgo.x);
                ffma2(acc[m][3], ad, bgo.y);
            }
        }
    }
}

// C[32 x 128] += A[32 x K] * Wt[K x 128] (fc). acc[m][h] pairs cols 4ln+2h..+1.
template <int K, int LDA>
__device__ __forceinline__ void gemm128f(u64t acc[4][2],
                                         const float* __restrict__ As,
                                         const float* __restrict__ Wt,
                                         int w, int ln)
{
#pragma unroll 2
    for (int kk = 0; kk < K; kk += 4) {
        float4 a[4];
#pragma unroll
        for (int m = 0; m < 4; ++m)
            a[m] = *(const float4*)(As + (w * 4 + m) * LDA + kk);
#pragma unroll
        for (int e = 0; e < 4; ++e) {
            ulonglong2 b = *(const ulonglong2*)(Wt + (kk + e) * 128 + ln * 4);
            float av[4] = {e == 0 ? a[0].x : e == 1 ? a[0].y : e == 2 ? a[0].z : a[0].w,
                           e == 0 ? a[1].x : e == 1 ? a[1].y : e == 2 ? a[1].z : a[1].w,
                           e == 0 ? a[2].x : e == 1 ? a[2].y : e == 2 ? a[2].z : a[2].w,
                           e == 0 ? a[3].x : e == 1 ? a[3].y : e == 2 ? a[3].z : a[3].w};
#pragma unroll
            for (int m = 0; m < 4; ++m) {
                u64t ad = dup1(av[m]);
                ffma2(acc[m][0], ad, b.x);
                ffma2(acc[m][1], ad, b.y);
            }
        }
    }
}

// Fused LSTM cell epilogue: acc holds gate pairs (i,f,g,o); c is persistent
// per-thread cell state; h pair written straight to SMEM.
__device__ __forceinline__ void cell_update(u64t acc[4][4], float2 c[4],
                                            float* __restrict__ hdst,
                                            int w, int ln)
{
#pragma unroll
    for (int m = 0; m < 4; ++m) {
        float ix, iy, fx, fy, gx, gy, ox, oy;
        unpack2(acc[m][0], ix, iy);
        unpack2(acc[m][1], fx, fy);
        unpack2(acc[m][2], gx, gy);
        unpack2(acc[m][3], ox, oy);
        float cx = sigf(fx) * c[m].x + sigf(ix) * tanhfast(gx);
        float cy = sigf(fy) * c[m].y + sigf(iy) * tanhfast(gy);
        c[m].x = cx; c[m].y = cy;
        *(float2*)(hdst + (w * 4 + m) * 64 + 2 * ln) =
            make_float2(sigf(ox) * tanhfast(cx), sigf(oy) * tanhfast(cy));
    }
}

// SMEM (floats): inp[32*128] | h0[32*64] | h1[32*64] | bias[640]
#define SM_INP 0
#define SM_H0  (32 * 128)
#define SM_H1  (SM_H0 + 32 * 64)
#define SM_B   (SM_H1 + 32 * 64)          // b0[256] | b1[256] | bfc[128]
#define SM_FLOATS (SM_B + 640)            // 8832 floats = 34.5 KB

__global__ __launch_bounds__(NTHR, 3) void lstm_kernel(
    const float* __restrict__ x,
    const float* __restrict__ b0,
    const float* __restrict__ b1,
    const float* __restrict__ bfc,
    float* __restrict__ out)
{
    extern __shared__ float sm[];
    float* s_inp = sm + SM_INP;
    float* s_h0  = sm + SM_H0;
    float* s_h1  = sm + SM_H1;
    float* s_b   = sm + SM_B;

    const int tid = threadIdx.x;
    const int w   = tid >> 5;
    const int ln  = tid & 31;
    const int rowg0 = blockIdx.x * ROWS;

    // Stage x tile (coalesced float4): 32 rows x 128 cols.
#pragma unroll 1
    for (int idx = tid; idx < 32 * 32; idx += NTHR) {
        int r = idx >> 5, cc = (idx & 31) << 2;
        *(float4*)(s_inp + r * 128 + cc) =
            *(const float4*)(x + (size_t)(rowg0 + r) * 128 + cc);
    }
#pragma unroll 1
    for (int idx = tid; idx < 32 * 64; idx += NTHR) {
        s_h0[idx] = 0.0f;
        s_h1[idx] = 0.0f;
    }
    // Stage biases to SMEM (keeps them out of registers).
    if (tid < 256) s_b[tid] = b0[tid];
    if (tid < 256) s_b[256 + tid] = b1[tid];
    if (tid < 128) s_b[512 + tid] = bfc[tid];

    // Persistent cell state: rows w*4..w*4+3, cols 2ln, 2ln+1.
    float2 c0[4], c1[4];
#pragma unroll
    for (int m = 0; m < 4; ++m) {
        c0[m] = make_float2(0.0f, 0.0f);
        c1[m] = make_float2(0.0f, 0.0f);
    }

    __syncthreads();

#pragma unroll 1
    for (int t = 0; t < NSTEP; ++t) {
        // ---- layer 0 gates ----
        {
            u64t acc[4][4];
            {
                u64t bini[4];
#pragma unroll
                for (int g = 0; g < 4; ++g)
                    bini[g] = *(const u64t*)(s_b + 64 * g + 2 * ln);
#pragma unroll
                for (int m = 0; m < 4; ++m)
#pragma unroll
                    for (int g = 0; g < 4; ++g) acc[m][g] = bini[g];
            }
            gemm256f<128, 128>(acc, s_inp, g_W0p, w, ln);
            gemm256f<64, 64>(acc, s_h0, g_W0p + 128 * 256, w, ln);
            __syncthreads();                 // all h0 reads done
            cell_update(acc, c0, s_h0, w, ln);
        }
        __syncthreads();

        // ---- layer 1 gates ----
        {
            u64t acc[4][4];
            {
                u64t bini[4];
#pragma unroll
                for (int g = 0; g < 4; ++g)
                    bini[g] = *(const u64t*)(s_b + 256 + 64 * g + 2 * ln);
#pragma unroll
                for (int m = 0; m < 4; ++m)
#pragma unroll
                    for (int g = 0; g < 4; ++g) acc[m][g] = bini[g];
            }
            gemm256f<64, 64>(acc, s_h0, g_W1p, w, ln);
            gemm256f<64, 64>(acc, s_h1, g_W1p + 64 * 256, w, ln);
            __syncthreads();                 // all h1 reads done
            cell_update(acc, c1, s_h1, w, ln);
        }
        __syncthreads();

        // ---- fc: y = h1 @ Wfc^T + bfc ; emit + feed back ----
        {
            u64t acc2[4][2];
            {
                u64t bf0 = *(const u64t*)(s_b + 512 + ln * 4);
                u64t bf1 = *(const u64t*)(s_b + 512 + ln * 4 + 2);
#pragma unroll
                for (int m = 0; m < 4; ++m) {
                    acc2[m][0] = bf0;
                    acc2[m][1] = bf1;
                }
            }
            gemm128f<64, 64>(acc2, s_h1, g_Wfct, w, ln);

            float* ystack = out + (size_t)(1 + t) * ((size_t)B_SZ * D_SZ);
#pragma unroll
            for (int m = 0; m < 4; ++m) {
                int row = w * 4 + m;
                float y0, y1, y2, y3;
                unpack2(acc2[m][0], y0, y1);
                unpack2(acc2[m][1], y2, y3);
                float4 v = make_float4(y0, y1, y2, y3);
                size_t go = (size_t)(rowg0 + row) * 128 + ln * 4;
                *(float4*)(ystack + go) = v;
                *(float4*)(s_inp + row * 128 + ln * 4) = v;   // next input
                if (t == NSTEP - 1) *(float4*)(out + go) = v; // y_last
            }
        }
        __syncthreads();
    }
}

extern "C" void kernel_launch(void* const* d_in, const int* in_sizes, int n_in,
                              void* d_out, int out_size)
{
    (void)in_sizes; (void)n_in; (void)out_size;
    const float* x    = (const float*)d_in[0];
    const float* Wih0 = (const float*)d_in[1];
    const float* Whh0 = (const float*)d_in[2];
    const float* b0   = (const float*)d_in[3];
    const float* Wih1 = (const float*)d_in[4];
    const float* Whh1 = (const float*)d_in[5];
    const float* b1   = (const float*)d_in[6];
    const float* Wfc  = (const float*)d_in[7];
    const float* bfc  = (const float*)d_in[8];
    float* out = (float*)d_out;

    pack_weights<<<(192 * 256 + 128 * 256 + 64 * 128 + 255) / 256, 256>>>(
        Wih0, Whh0, Wih1, Whh1, Wfc);

    cudaFuncSetAttribute(lstm_kernel,
                         cudaFuncAttributeMaxDynamicSharedMemorySize,
                         SM_FLOATS * sizeof(float));
    lstm_kernel<<<NCTA, NTHR, SM_FLOATS * sizeof(float)>>>(x, b0, b1, bfc, out);
}